// round 2
// baseline (speedup 1.0000x reference)
#include <cuda_runtime.h>
#include <math.h>
#include <stdint.h>

#define N_LEVELS 16
#define TBITS    19
#define TSIZE    (1u << TBITS)
#define HMASK    (TSIZE - 1u)
#define PRIME_Y  2654435761u

#define NCACHED  4          // levels 0..3 cached in smem (res 16,20,25,32)
#define CVERTS   2305       // 256+400+625+1024 vertices per grid
#define CHUNK    1024       // points per block
#define BLOCK    256

struct ScaleArr { float s[N_LEVELS]; };

__device__ __forceinline__ float2 pick_lo(float4 q) { return make_float2(q.x, q.y); }
__device__ __forceinline__ float2 pick_hi(float4 q) { return make_float2(q.z, q.w); }

// ---------------- main kernel: smem-cached coarse levels + paired fine loads
__global__ void __launch_bounds__(BLOCK) hashgrid2d_smem_kernel(
    const float2* __restrict__ x,
    const float2* __restrict__ feat,     // [2,16,T] float2
    const int*    __restrict__ gidx,
    float2*       __restrict__ out,      // [N,16] float2
    int N, ScaleArr sc)
{
    __shared__ float2 cache[2 * CVERTS];

    const int tid = threadIdx.x;

    // ---- fill smem dense tables for levels 0..3, both grids ----
    #pragma unroll
    for (int g = 0; g < 2; g++) {
        #pragma unroll
        for (int l = 0; l < NCACHED; l++) {
            const int res = (l == 0) ? 16 : (l == 1) ? 20 : (l == 2) ? 25 : 32;
            const int off = (l == 0) ? 0  : (l == 1) ? 256 : (l == 2) ? 656 : 1281;
            const int nv  = res * res;
            const float2* fb = feat + ((size_t)(g * N_LEVELS + l) << TBITS);
            for (int v = tid; v < nv; v += BLOCK) {
                unsigned vy = (unsigned)(v / res);
                unsigned vx = (unsigned)(v - (int)vy * res);
                unsigned h  = (vx ^ (vy * PRIME_Y)) & HMASK;
                cache[g * CVERTS + off + v] = __ldg(fb + h);
            }
        }
    }
    __syncthreads();

    const int level = tid & 15;
    const float s   = sc.s[level];
    const int res_l = (level == 0) ? 16 : (level == 1) ? 20 : (level == 2) ? 25 : 32;
    const int off_l = (level == 0) ? 0  : (level == 1) ? 256 : (level == 2) ? 656 : 1281;

    const size_t pbase = (size_t)blockIdx.x * CHUNK;

    #pragma unroll 1
    for (int k = 0; k < (CHUNK * N_LEVELS) / BLOCK; k++) {
        const int item = tid + k * BLOCK;          // 0 .. CHUNK*16-1
        const size_t p = pbase + (size_t)(item >> 4);
        if (p >= (size_t)N) break;                  // p ascending in k per thread

        const float2 xy = __ldg(&x[p]);
        const int g     = __ldg(&gidx[p]);

        const float px = xy.x * s;
        const float py = xy.y * s;
        const float fx = floorf(px);
        const float fy = floorf(py);
        const float wx = px - fx;
        const float wy = py - fy;
        const unsigned ix = (unsigned)(int)fx;
        const unsigned iy = (unsigned)(int)fy;

        float2 f00, f10, f01, f11;

        if (level < NCACHED) {
            const int b = g * CVERTS + off_l + (int)iy * res_l + (int)ix;
            f00 = cache[b];
            f10 = cache[b + 1];
            f01 = cache[b + res_l];
            f11 = cache[b + res_l + 1];
        } else {
            const float2* __restrict__ base =
                feat + ((size_t)(g * N_LEVELS + level) << TBITS);
            const unsigned hy0 = iy * PRIME_Y;
            const unsigned hy1 = (iy + 1u) * PRIME_Y;
            const unsigned h00 = (ix ^ hy0) & HMASK;
            const unsigned h01 = (ix ^ hy1) & HMASK;

            if ((ix & 1u) == 0u) {
                // corners (ix, ix+1) differ only in bit0 of the hash: one LDG.128 each row
                const float4 q0 = __ldg((const float4*)base + (h00 >> 1));
                const float4 q1 = __ldg((const float4*)base + (h01 >> 1));
                if (h00 & 1u) { f00 = pick_hi(q0); f10 = pick_lo(q0); }
                else          { f00 = pick_lo(q0); f10 = pick_hi(q0); }
                if (h01 & 1u) { f01 = pick_hi(q1); f11 = pick_lo(q1); }
                else          { f01 = pick_lo(q1); f11 = pick_hi(q1); }
            } else {
                const unsigned h10 = ((ix + 1u) ^ hy0) & HMASK;
                const unsigned h11 = ((ix + 1u) ^ hy1) & HMASK;
                f00 = __ldg(base + h00);
                f10 = __ldg(base + h10);
                f01 = __ldg(base + h01);
                f11 = __ldg(base + h11);
            }
        }

        const float w00 = (1.0f - wx) * (1.0f - wy);
        const float w10 = wx * (1.0f - wy);
        const float w01 = (1.0f - wx) * wy;
        const float w11 = wx * wy;

        float2 o;
        o.x = w00 * f00.x + w10 * f10.x + w01 * f01.x + w11 * f11.x;
        o.y = w00 * f00.y + w10 * f10.y + w01 * f01.y + w11 * f11.y;

        out[pbase * N_LEVELS + item] = o;   // == out[p*16 + level], coalesced
    }
}

// ---------------- fallback: paired loads only (if host-resolutions mismatch)
__global__ void __launch_bounds__(256) hashgrid2d_fallback_kernel(
    const float2* __restrict__ x,
    const float2* __restrict__ feat,
    const int*    __restrict__ gidx,
    float2*       __restrict__ out,
    int n_total, ScaleArr sc)
{
    int t = blockIdx.x * blockDim.x + threadIdx.x;
    if (t >= n_total) return;
    int level = t & 15;
    int p     = t >> 4;

    float2 xy = __ldg(&x[p]);
    int g     = __ldg(&gidx[p]);
    float s   = sc.s[level];
    float px = xy.x * s, py = xy.y * s;
    float fx = floorf(px), fy = floorf(py);
    float wx = px - fx, wy = py - fy;
    unsigned ix = (unsigned)(int)fx, iy = (unsigned)(int)fy;

    const float2* __restrict__ base = feat + ((size_t)(g * N_LEVELS + level) << TBITS);
    unsigned hy0 = iy * PRIME_Y, hy1 = (iy + 1u) * PRIME_Y;
    unsigned h00 = (ix ^ hy0) & HMASK, h01 = (ix ^ hy1) & HMASK;

    float2 f00, f10, f01, f11;
    if ((ix & 1u) == 0u) {
        float4 q0 = __ldg((const float4*)base + (h00 >> 1));
        float4 q1 = __ldg((const float4*)base + (h01 >> 1));
        if (h00 & 1u) { f00 = pick_hi(q0); f10 = pick_lo(q0); }
        else          { f00 = pick_lo(q0); f10 = pick_hi(q0); }
        if (h01 & 1u) { f01 = pick_hi(q1); f11 = pick_lo(q1); }
        else          { f01 = pick_lo(q1); f11 = pick_hi(q1); }
    } else {
        unsigned h10 = ((ix + 1u) ^ hy0) & HMASK;
        unsigned h11 = ((ix + 1u) ^ hy1) & HMASK;
        f00 = __ldg(base + h00);
        f10 = __ldg(base + h10);
        f01 = __ldg(base + h01);
        f11 = __ldg(base + h11);
    }

    float w00 = (1.0f - wx) * (1.0f - wy);
    float w10 = wx * (1.0f - wy);
    float w01 = (1.0f - wx) * wy;
    float w11 = wx * wy;

    float2 o;
    o.x = w00 * f00.x + w10 * f10.x + w01 * f01.x + w11 * f11.x;
    o.y = w00 * f00.y + w10 * f10.y + w01 * f01.y + w11 * f11.y;
    out[t] = o;
}

extern "C" void kernel_launch(void* const* d_in, const int* in_sizes, int n_in,
                              void* d_out, int out_size)
{
    const float2* x    = (const float2*)d_in[0];
    const float2* feat = (const float2*)d_in[1];
    const int*    gidx = (const int*)d_in[2];
    float2*       out  = (float2*)d_out;

    int N = in_sizes[0] / 2;

    // Per-level res with the same libm double math as the reference.
    ScaleArr sc;
    int res_i[N_LEVELS];
    double bw = exp((log(512.0) - log(16.0)) / (double)(N_LEVELS - 1));
    for (int i = 0; i < N_LEVELS; i++) {
        res_i[i] = (int)(16.0 * pow(bw, (double)i));
        sc.s[i]  = (float)(res_i[i] - 1);
    }

    bool cached_ok = (res_i[0] == 16 && res_i[1] == 20 &&
                      res_i[2] == 25 && res_i[3] == 32);

    if (cached_ok) {
        int nblocks = (N + CHUNK - 1) / CHUNK;
        hashgrid2d_smem_kernel<<<nblocks, BLOCK>>>(x, feat, gidx, out, N, sc);
    } else {
        int n_total = N * N_LEVELS;
        hashgrid2d_fallback_kernel<<<(n_total + 255) / 256, 256>>>(
            x, feat, gidx, out, n_total, sc);
    }
}

// round 3
// speedup vs baseline: 1.9217x; 1.9217x over previous
#include <cuda_runtime.h>
#include <math.h>
#include <stdint.h>

// HashGrid2D, flat layout: one thread per (point, level), 16M threads.
// XOR-pair merging: for even ix, the two x-adjacent corners share one
// 16B-aligned float4 -> LDG.128 replaces two LDG.64 (25% fewer L1tex
// sector-requests, the binding resource per R1 ncu).

#define N_LEVELS 16
#define TBITS    19
#define TSIZE    (1u << TBITS)
#define HMASK    (TSIZE - 1u)
#define PRIME_Y  2654435761u

struct ScaleArr { float s[N_LEVELS]; };

__global__ void __launch_bounds__(256) hashgrid2d_paired_kernel(
    const float2* __restrict__ x,        // [N]
    const float2* __restrict__ feat,     // [2,16,T] float2
    const int*    __restrict__ gidx,     // [N]
    float2*       __restrict__ out,      // [N,16] float2
    int n_total, ScaleArr sc)
{
    int t = blockIdx.x * blockDim.x + threadIdx.x;
    if (t >= n_total) return;

    const int level = t & (N_LEVELS - 1);
    const int p     = t >> 4;

    const float2 xy = __ldg(&x[p]);
    const int g     = __ldg(&gidx[p]);

    const float s  = sc.s[level];
    const float px = xy.x * s;
    const float py = xy.y * s;
    const float fx = floorf(px);
    const float fy = floorf(py);
    const float wx = px - fx;
    const float wy = py - fy;
    const unsigned ix = (unsigned)(int)fx;
    const unsigned iy = (unsigned)(int)fy;

    const float2* __restrict__ base =
        feat + ((size_t)(g * N_LEVELS + level) << TBITS);

    const unsigned hy0 = iy * PRIME_Y;
    const unsigned hy1 = (iy + 1u) * PRIME_Y;
    const unsigned h00 = (ix ^ hy0) & HMASK;
    const unsigned h01 = (ix ^ hy1) & HMASK;

    float2 f00, f10, f01, f11;

    if ((ix & 1u) == 0u) {
        // corners ix and ix+1 differ only in hash bit 0 -> same float4
        const float4 q0 = __ldg((const float4*)base + (h00 >> 1));
        const float4 q1 = __ldg((const float4*)base + (h01 >> 1));
        if (h00 & 1u) { f00 = make_float2(q0.z, q0.w); f10 = make_float2(q0.x, q0.y); }
        else          { f00 = make_float2(q0.x, q0.y); f10 = make_float2(q0.z, q0.w); }
        if (h01 & 1u) { f01 = make_float2(q1.z, q1.w); f11 = make_float2(q1.x, q1.y); }
        else          { f01 = make_float2(q1.x, q1.y); f11 = make_float2(q1.z, q1.w); }
    } else {
        const unsigned h10 = ((ix + 1u) ^ hy0) & HMASK;
        const unsigned h11 = ((ix + 1u) ^ hy1) & HMASK;
        f00 = __ldg(base + h00);
        f10 = __ldg(base + h10);
        f01 = __ldg(base + h01);
        f11 = __ldg(base + h11);
    }

    const float w00 = (1.0f - wx) * (1.0f - wy);
    const float w10 = wx * (1.0f - wy);
    const float w01 = (1.0f - wx) * wy;
    const float w11 = wx * wy;

    float2 o;
    o.x = w00 * f00.x + w10 * f10.x + w01 * f01.x + w11 * f11.x;
    o.y = w00 * f00.y + w10 * f10.y + w01 * f01.y + w11 * f11.y;

    out[t] = o;
}

extern "C" void kernel_launch(void* const* d_in, const int* in_sizes, int n_in,
                              void* d_out, int out_size)
{
    const float2* x    = (const float2*)d_in[0];
    const float2* feat = (const float2*)d_in[1];
    const int*    gidx = (const int*)d_in[2];
    float2*       out  = (float2*)d_out;

    int N = in_sizes[0] / 2;
    int n_total = N * N_LEVELS;

    // Per-level scale = (res - 1), same libm double math as the reference.
    ScaleArr sc;
    double bw = exp((log(512.0) - log(16.0)) / (double)(N_LEVELS - 1));
    for (int i = 0; i < N_LEVELS; i++) {
        int res = (int)(16.0 * pow(bw, (double)i));
        sc.s[i] = (float)(res - 1);
    }

    int threads = 256;
    int blocks  = (n_total + threads - 1) / threads;
    hashgrid2d_paired_kernel<<<blocks, threads>>>(x, feat, gidx, out, n_total, sc);
}